// round 1
// baseline (speedup 1.0000x reference)
#include <cuda_runtime.h>
#include <math.h>

#define Bn 256
#define Sn 128
#define ASn 5
#define En 300
#define Hn 300
#define Pn 3
#define NG 1200   // 4*H
#define Dn 601    // 2*H+1

// ------------------------- scratch (device globals) -------------------------
__device__ float g_x[Bn*Sn*En];          // embedded memory (B,S,E)
__device__ float g_pre_f[(size_t)Bn*Sn*NG];  // x@w_ih_f.T + b_ih_f + b_hh_f
__device__ float g_pre_b[(size_t)Bn*Sn*NG];
__device__ float g_outf[Bn*Sn*Hn];       // forward lstm outputs
__device__ float g_outrev[Bn*Sn*Hn];     // backward lstm outputs (rev order)
__device__ float g_mem[(size_t)Bn*Sn*Dn];    // locationed memory (B,S,601)
__device__ float g_whhT_f[Hn*NG];        // w_hh_f transposed (300 x 1200)
__device__ float g_whhT_b[Hn*NG];
__device__ float g_gwihT[Dn*900];        // gru_w_ih transposed (601 x 900)
__device__ float g_gwhhT[Hn*900];        // gru_w_hh transposed (300 x 900)
__device__ float g_aspect[Bn*En];
__device__ float g_et[Bn*En];
__device__ float g_it[Bn*Dn];
__device__ int   g_len[3*Bn];            // [b]=mem_len, [B+b]=left_len, [2B+b]=asp_len

__device__ __forceinline__ float sigf(float x){ return 1.f/(1.f+expf(-x)); }

// ------------------------- lengths -------------------------
__global__ void lengths_kernel(const int* __restrict__ raw,
                               const int* __restrict__ aidx,
                               const int* __restrict__ left)
{
    int b = blockIdx.x;
    int t = threadIdx.x; // 128
    int c1 = raw[b*Sn+t]  != 0;
    int c2 = left[b*Sn+t] != 0;
    int c3 = (t < ASn) ? (aidx[b*ASn+t] != 0) : 0;
    int mlen = __syncthreads_count(c1);
    int llen = __syncthreads_count(c2);
    int alen = __syncthreads_count(c3);
    if (t == 0){ g_len[b] = mlen; g_len[Bn+b] = llen; g_len[2*Bn+b] = alen; }
}

// ------------------------- embedding gather -------------------------
__global__ void embed_kernel(const int* __restrict__ raw, const float* __restrict__ emb)
{
    int i = blockIdx.x*blockDim.x + threadIdx.x;
    const int total = Bn*Sn*(En/4); // 75 float4 per row
    if (i >= total) return;
    int row = i / 75;
    int c   = i % 75;
    int v = raw[row];
    ((float4*)g_x)[(size_t)row*75 + c] = ((const float4*)emb)[(size_t)v*75 + c];
}

// ------------------------- generic transpose into scratch -------------------------
__global__ void transpose_kernel(const float* __restrict__ in, int R, int C, int which)
{
    float* out = (which==0) ? g_whhT_f : (which==1) ? g_whhT_b
               : (which==2) ? g_gwihT  : g_gwhhT;
    __shared__ float tile[32][33];
    int c0 = blockIdx.x*32, r0 = blockIdx.y*32;
    int x = threadIdx.x, y = threadIdx.y;
    #pragma unroll
    for (int i = 0; i < 32; i += 8){
        int r = r0 + y + i, c = c0 + x;
        if (r < R && c < C) tile[y+i][x] = in[(size_t)r*C + c];
    }
    __syncthreads();
    #pragma unroll
    for (int i = 0; i < 32; i += 8){
        int r = r0 + x, c = c0 + y + i;
        if (r < R && c < C) out[(size_t)c*R + r] = tile[x][y+i];
    }
}

// ------------------------- input GEMM: pre = X(32768,300) @ W(1200,300)^T + b1 + b2 -----
__global__ void gemm_pre_kernel(const float* __restrict__ W,
                                const float* __restrict__ b1,
                                const float* __restrict__ b2,
                                int which)
{
    const int N = NG, K = En;
    const float* A = g_x;
    float* C = which ? g_pre_b : g_pre_f;
    __shared__ float As[8][128];
    __shared__ float Bs[8][128];
    int t  = threadIdx.x;            // 256
    int n0 = blockIdx.x * 128;
    int m0 = blockIdx.y * 128;
    int tx = t & 15, ty = t >> 4;
    int lr = t >> 1;                  // 0..127
    int lk = (t & 1) * 4;             // 0 or 4
    float acc[8][8];
    #pragma unroll
    for (int i = 0; i < 8; i++)
        #pragma unroll
        for (int j = 0; j < 8; j++) acc[i][j] = 0.f;

    for (int kt = 0; kt < K; kt += 8){
        int gk = kt + lk;
        { // A tile (no M guard: M=32768 multiple of 128)
            const float* p = A + (size_t)(m0+lr)*K + gk;
            float4 v;
            if (gk + 4 <= K) v = *(const float4*)p;
            else {
                v.x = (gk   < K) ? p[0] : 0.f;
                v.y = (gk+1 < K) ? p[1] : 0.f;
                v.z = (gk+2 < K) ? p[2] : 0.f;
                v.w = (gk+3 < K) ? p[3] : 0.f;
            }
            As[lk  ][lr] = v.x; As[lk+1][lr] = v.y;
            As[lk+2][lr] = v.z; As[lk+3][lr] = v.w;
        }
        { // W tile
            int gn = n0 + lr;
            float4 v = make_float4(0.f,0.f,0.f,0.f);
            if (gn < N){
                const float* p = W + (size_t)gn*K + gk;
                if (gk + 4 <= K) v = *(const float4*)p;
                else {
                    if (gk   < K) v.x = p[0];
                    if (gk+1 < K) v.y = p[1];
                    if (gk+2 < K) v.z = p[2];
                    if (gk+3 < K) v.w = p[3];
                }
            }
            Bs[lk  ][lr] = v.x; Bs[lk+1][lr] = v.y;
            Bs[lk+2][lr] = v.z; Bs[lk+3][lr] = v.w;
        }
        __syncthreads();
        #pragma unroll
        for (int kk = 0; kk < 8; kk++){
            float a[8], bb[8];
            *(float4*)&a[0]  = *(const float4*)&As[kk][ty*8];
            *(float4*)&a[4]  = *(const float4*)&As[kk][ty*8+4];
            *(float4*)&bb[0] = *(const float4*)&Bs[kk][tx*8];
            *(float4*)&bb[4] = *(const float4*)&Bs[kk][tx*8+4];
            #pragma unroll
            for (int i = 0; i < 8; i++)
                #pragma unroll
                for (int j = 0; j < 8; j++)
                    acc[i][j] += a[i]*bb[j];
        }
        __syncthreads();
    }
    #pragma unroll
    for (int i = 0; i < 8; i++){
        int gm = m0 + ty*8 + i;
        #pragma unroll
        for (int jq = 0; jq < 8; jq += 4){
            int gn = n0 + tx*8 + jq;
            if (gn < N){
                float4 v;
                v.x = acc[i][jq  ] + b1[gn  ] + b2[gn  ];
                v.y = acc[i][jq+1] + b1[gn+1] + b2[gn+1];
                v.z = acc[i][jq+2] + b1[gn+2] + b2[gn+2];
                v.w = acc[i][jq+3] + b1[gn+3] + b2[gn+3];
                *(float4*)&C[(size_t)gm*N + gn] = v;
            }
        }
    }
}

// ------------------------- persistent BiLSTM recurrence -------------------------
// grid (64, 2): blockIdx.y = direction; each block owns 4 batch rows.
// threads 640: t<600 active for gates: gh=t/300 selects gate pair, j=t%300.
__global__ void lstm_kernel()
{
    int dir = blockIdx.y;
    const float* pre  = dir ? g_pre_b  : g_pre_f;
    const float* whhT = dir ? g_whhT_b : g_whhT_f;
    float* out        = dir ? g_outrev : g_outf;
    int b0 = blockIdx.x * 4;

    __shared__ float h_s[4][Hn];
    __shared__ float c_s[4][Hn];
    __shared__ float gsm[4][4][Hn];   // [gate][row][j] after activation

    int t = threadIdx.x;
    int lens[4];
    #pragma unroll
    for (int r = 0; r < 4; r++) lens[r] = g_len[b0 + r];
    int maxlen = max(max(lens[0],lens[1]), max(lens[2],lens[3]));

    for (int i = t; i < 4*Hn; i += blockDim.x){
        ((float*)h_s)[i] = 0.f;
        ((float*)c_s)[i] = 0.f;
    }
    __syncthreads();

    int gh = t / 300;
    int j  = t % 300;
    bool active = (t < 600);

    for (int step = 0; step < Sn; step++){
        if (active && step < maxlen){
            int g0 = gh*2;
            float acc[2][4];
            #pragma unroll
            for (int r = 0; r < 4; r++){
                int L = lens[r];
                if (step < L){
                    int pos = dir ? (L-1-step) : step;
                    const float* p = pre + ((size_t)(b0+r)*Sn + pos)*NG;
                    acc[0][r] = p[g0*300 + j];
                    acc[1][r] = p[g0*300 + 300 + j];
                } else { acc[0][r] = 0.f; acc[1][r] = 0.f; }
            }
            const float* wp = whhT + g0*300 + j;
            #pragma unroll 4
            for (int k = 0; k < Hn; k++){
                float wa = wp[(size_t)k*NG];
                float wb = wp[(size_t)k*NG + 300];
                float h0 = h_s[0][k], h1 = h_s[1][k], h2 = h_s[2][k], h3 = h_s[3][k];
                acc[0][0] += wa*h0; acc[0][1] += wa*h1; acc[0][2] += wa*h2; acc[0][3] += wa*h3;
                acc[1][0] += wb*h0; acc[1][1] += wb*h1; acc[1][2] += wb*h2; acc[1][3] += wb*h3;
            }
            if (gh == 0){
                #pragma unroll
                for (int r = 0; r < 4; r++){
                    gsm[0][r][j] = sigf(acc[0][r]);  // i
                    gsm[1][r][j] = sigf(acc[1][r]);  // f
                }
            } else {
                #pragma unroll
                for (int r = 0; r < 4; r++){
                    gsm[2][r][j] = tanhf(acc[0][r]); // g
                    gsm[3][r][j] = sigf(acc[1][r]);  // o
                }
            }
        }
        __syncthreads();
        if (t < 300){
            #pragma unroll
            for (int r = 0; r < 4; r++){
                float* op = out + ((size_t)(b0+r)*Sn + step)*Hn + t;
                if (step < lens[r]){
                    float c = gsm[1][r][t]*c_s[r][t] + gsm[0][r][t]*gsm[2][r][t];
                    float h = gsm[3][r][t]*tanhf(c);
                    c_s[r][t] = c;
                    h_s[r][t] = h;
                    *op = h;
                } else {
                    *op = 0.f;
                }
            }
        }
        __syncthreads();
    }
}

// ------------------------- locationed memory -------------------------
__global__ void locmem_kernel()
{
    int b = blockIdx.x;
    int s = blockIdx.y;
    int mlen = g_len[b];
    int llen = g_len[Bn+b];
    int alen = g_len[2*Bn+b];
    int a_s = llen, a_e = llen + alen;
    float u, l;
    if (s < a_s)      { u = (float)(s - a_s); l = (float)(a_s - s); }
    else if (s < a_e) { u = 0.f; l = 0.f; }
    else              { u = (float)(s - a_e + 1); l = u; }
    bool valid = s < mlen;
    if (!valid) u = 0.f;
    float w = valid ? (1.f - l/(float)mlen) : 1.f;

    float* mo = g_mem + ((size_t)b*Sn + s)*Dn;
    const float* of = g_outf + ((size_t)b*Sn + s)*Hn;
    const float* orv = valid ? (g_outrev + ((size_t)b*Sn + (mlen-1-s))*Hn) : (const float*)0;
    int t = threadIdx.x;
    for (int d = t; d < Dn; d += blockDim.x){
        float v;
        if (d < Hn)        v = of[d] * w;
        else if (d < 2*Hn) v = (orv ? orv[d-Hn] : 0.f) * w;
        else               v = u;
        mo[d] = v;
    }
}

// ------------------------- aspect mean + et init -------------------------
__global__ void aspect_kernel(const int* __restrict__ aidx, const float* __restrict__ emb)
{
    int b = blockIdx.x;
    int t = threadIdx.x; // 320
    if (t < En){
        float s = 0.f;
        #pragma unroll
        for (int jj = 0; jj < ASn; jj++){
            int v = aidx[b*ASn + jj];
            s += emb[(size_t)v*En + t];
        }
        g_aspect[b*En + t] = s / (float)g_len[2*Bn + b];
        g_et[b*En + t] = 0.f;
    }
}

// ------------------------- attention (per hop): g, softmax, i_t -------------------------
__global__ void att_kernel(const float* __restrict__ att_w, const float* __restrict__ att_b)
{
    int b = blockIdx.x;
    int t = threadIdx.x; // 256
    __shared__ float red[256];
    __shared__ float alpha[Sn];
    __shared__ float base_s;

    // et . att_w[601:901] + aspect . att_w[901:1201]
    float p = 0.f;
    for (int d = t; d < En; d += 256)
        p += g_et[b*En+d]*att_w[Dn+d] + g_aspect[b*En+d]*att_w[Dn+En+d];
    red[t] = p; __syncthreads();
    for (int s = 128; s > 0; s >>= 1){ if (t < s) red[t] += red[t+s]; __syncthreads(); }
    if (t == 0) base_s = red[0] + att_b[0];
    __syncthreads();

    // g[s] = mem[b,s,:] . att_w[0:601] + base
    int warp = t >> 5, lane = t & 31;
    for (int s = warp; s < Sn; s += 8){
        const float* mrow = g_mem + ((size_t)b*Sn + s)*Dn;
        float acc = 0.f;
        for (int d = lane; d < Dn; d += 32) acc += mrow[d]*att_w[d];
        #pragma unroll
        for (int o = 16; o > 0; o >>= 1) acc += __shfl_down_sync(0xffffffffu, acc, o);
        if (lane == 0) alpha[s] = acc + base_s;
    }
    __syncthreads();

    // softmax over full S (matches reference: no mask)
    red[t] = (t < Sn) ? alpha[t] : -1e30f;
    __syncthreads();
    for (int s = 128; s > 0; s >>= 1){ if (t < s) red[t] = fmaxf(red[t], red[t+s]); __syncthreads(); }
    float mx = red[0]; __syncthreads();
    float e = 0.f;
    if (t < Sn){ e = expf(alpha[t] - mx); alpha[t] = e; }
    red[t] = e; __syncthreads();
    for (int s = 128; s > 0; s >>= 1){ if (t < s) red[t] += red[t+s]; __syncthreads(); }
    float inv = 1.f / red[0]; __syncthreads();
    if (t < Sn) alpha[t] *= inv;
    __syncthreads();

    // i_t[d] = sum_s alpha[s] * mem[b,s,d]
    for (int d = t; d < Dn; d += 256){
        float acc = 0.f;
        const float* mp = g_mem + (size_t)b*Sn*Dn + d;
        #pragma unroll 4
        for (int s = 0; s < Sn; s++) acc += alpha[s]*mp[(size_t)s*Dn];
        g_it[b*Dn + d] = acc;
    }
}

// ------------------------- GRU cell (per hop) -------------------------
__global__ void gru_kernel(const float* __restrict__ b_ih, const float* __restrict__ b_hh)
{
    int b = blockIdx.x;
    int t = threadIdx.x; // 320
    __shared__ float it_s[Dn];
    __shared__ float et_s[En];
    for (int d = t; d < Dn; d += 320) it_s[d] = g_it[b*Dn + d];
    for (int d = t; d < En; d += 320) et_s[d] = g_et[b*En + d];
    __syncthreads();
    if (t < 300){
        int j = t;
        float gi0 = b_ih[j], gi1 = b_ih[300+j], gi2 = b_ih[600+j];
        const float* wp = g_gwihT + j;
        #pragma unroll 4
        for (int d = 0; d < Dn; d++){
            float x = it_s[d];
            gi0 += x*wp[(size_t)d*900];
            gi1 += x*wp[(size_t)d*900 + 300];
            gi2 += x*wp[(size_t)d*900 + 600];
        }
        float gh0 = b_hh[j], gh1 = b_hh[300+j], gh2 = b_hh[600+j];
        const float* hp = g_gwhhT + j;
        #pragma unroll 4
        for (int d = 0; d < En; d++){
            float x = et_s[d];
            gh0 += x*hp[(size_t)d*900];
            gh1 += x*hp[(size_t)d*900 + 300];
            gh2 += x*hp[(size_t)d*900 + 600];
        }
        float r = sigf(gi0 + gh0);
        float z = sigf(gi1 + gh1);
        float n = tanhf(gi2 + r*gh2);
        g_et[b*En + j] = (1.f - z)*n + z*et_s[j];
    }
}

// ------------------------- dense head -------------------------
__global__ void dense_kernel(const float* __restrict__ dw, const float* __restrict__ db,
                             float* __restrict__ out)
{
    int b = blockIdx.x;
    int t = threadIdx.x; // 96
    int p = t >> 5, lane = t & 31;
    float acc = 0.f;
    for (int d = lane; d < En; d += 32) acc += g_et[b*En + d]*dw[p*En + d];
    #pragma unroll
    for (int o = 16; o > 0; o >>= 1) acc += __shfl_down_sync(0xffffffffu, acc, o);
    if (lane == 0) out[b*Pn + p] = acc + db[p];
}

// ------------------------- launch -------------------------
extern "C" void kernel_launch(void* const* d_in, const int* in_sizes, int n_in,
                              void* d_out, int out_size)
{
    const int*   raw    = (const int*)d_in[0];
    const int*   aidx   = (const int*)d_in[1];
    const int*   left   = (const int*)d_in[2];
    const float* emb    = (const float*)d_in[3];
    const float* w_ih_f = (const float*)d_in[4];
    const float* w_hh_f = (const float*)d_in[5];
    const float* b_ih_f = (const float*)d_in[6];
    const float* b_hh_f = (const float*)d_in[7];
    const float* w_ih_b = (const float*)d_in[8];
    const float* w_hh_b = (const float*)d_in[9];
    const float* b_ih_b = (const float*)d_in[10];
    const float* b_hh_b = (const float*)d_in[11];
    const float* att_w  = (const float*)d_in[12];
    const float* att_b  = (const float*)d_in[13];
    const float* gw_ih  = (const float*)d_in[14];
    const float* gw_hh  = (const float*)d_in[15];
    const float* gb_ih  = (const float*)d_in[16];
    const float* gb_hh  = (const float*)d_in[17];
    const float* dw     = (const float*)d_in[18];
    const float* db     = (const float*)d_in[19];
    float* out = (float*)d_out;

    lengths_kernel<<<Bn, Sn>>>(raw, aidx, left);
    embed_kernel<<<(Bn*Sn*75 + 255)/256, 256>>>(raw, emb);

    transpose_kernel<<<dim3(10,38), dim3(32,8)>>>(w_hh_f, NG, Hn, 0);
    transpose_kernel<<<dim3(10,38), dim3(32,8)>>>(w_hh_b, NG, Hn, 1);
    transpose_kernel<<<dim3(19,29), dim3(32,8)>>>(gw_ih, 900, Dn, 2);
    transpose_kernel<<<dim3(10,29), dim3(32,8)>>>(gw_hh, 900, Hn, 3);

    gemm_pre_kernel<<<dim3(10,256), 256>>>(w_ih_f, b_ih_f, b_hh_f, 0);
    gemm_pre_kernel<<<dim3(10,256), 256>>>(w_ih_b, b_ih_b, b_hh_b, 1);

    lstm_kernel<<<dim3(64,2), 640>>>();

    locmem_kernel<<<dim3(Bn,Sn), 256>>>();
    aspect_kernel<<<Bn, 320>>>(aidx, emb);

    for (int hop = 0; hop < 3; hop++){
        att_kernel<<<Bn, 256>>>(att_w, att_b);
        gru_kernel<<<Bn, 320>>>(gb_ih, gb_hh);
    }
    dense_kernel<<<Bn, 96>>>(dw, db, out);
}

// round 2
// speedup vs baseline: 1.3170x; 1.3170x over previous
#include <cuda_runtime.h>
#include <math.h>

#define Bn 256
#define Sn 128
#define ASn 5
#define En 300
#define Hn 300
#define Pn 3
#define NG 1200   // 4*H
#define Dn 601    // 2*H+1
#define KP 304    // padded K for gemm (300 -> 304)
#define NP 2432   // padded N for gemm (2400 -> 2432)

// ------------------------- scratch (device globals) -------------------------
__device__ float g_xp[(size_t)Bn*Sn*KP];       // embedded memory padded (B*S, 304)
__device__ float g_wp[(size_t)NP*KP];          // stacked padded input weights
__device__ float g_bs[NP];                     // summed biases
__device__ float g_pre[(size_t)Bn*Sn*NP];      // x@W^T + b (both dirs stacked)
__device__ float g_outf[(size_t)Bn*Sn*Hn];     // forward lstm outputs
__device__ float g_outrev[(size_t)Bn*Sn*Hn];   // backward lstm outputs (rev order)
__device__ float g_mem[(size_t)Bn*Sn*Dn];      // locationed memory (B,S,601)
__device__ float g_whhT_f[Hn*NG];              // w_hh_f transposed (300 x 1200) [k][row]
__device__ float g_whhT_b[Hn*NG];
__device__ float g_gwihT[Dn*900];              // gru_w_ih transposed (601 x 900)
__device__ float g_gwhhT[Hn*900];              // gru_w_hh transposed (300 x 900)
__device__ float g_aspect[Bn*En];
__device__ float g_et[Bn*En];
__device__ float g_it[Bn*Dn];
__device__ int   g_len[3*Bn];                  // [b]=mem_len, [B+b]=left_len, [2B+b]=asp_len
__device__ float g_hx[2*2*32*300*8];           // h exchange: [parity][dir][bg][j][r]
__device__ unsigned g_sync[128];               // per-block step flags

__device__ __forceinline__ float sigf(float x){ return 1.f/(1.f+expf(-x)); }

// ------------------------- lengths -------------------------
__global__ void lengths_kernel(const int* __restrict__ raw,
                               const int* __restrict__ aidx,
                               const int* __restrict__ left)
{
    int b = blockIdx.x;
    int t = threadIdx.x; // 128
    int c1 = raw[b*Sn+t]  != 0;
    int c2 = left[b*Sn+t] != 0;
    int c3 = (t < ASn) ? (aidx[b*ASn+t] != 0) : 0;
    int mlen = __syncthreads_count(c1);
    int llen = __syncthreads_count(c2);
    int alen = __syncthreads_count(c3);
    if (t == 0){ g_len[b] = mlen; g_len[Bn+b] = llen; g_len[2*Bn+b] = alen; }
}

__global__ void zero_sync_kernel()
{
    if (threadIdx.x < 128) g_sync[threadIdx.x] = 0u;
}

// ------------------------- embedding gather (padded) -------------------------
__global__ void embed_kernel(const int* __restrict__ raw, const float* __restrict__ emb)
{
    int i = blockIdx.x*blockDim.x + threadIdx.x;
    const int total = Bn*Sn*76; // 76 float4 per padded row
    if (i >= total) return;
    int row = i / 76;
    int c   = i % 76;
    float4 v = make_float4(0.f,0.f,0.f,0.f);
    if (c < 75){
        int tok = raw[row];
        v = ((const float4*)emb)[(size_t)tok*75 + c];
    }
    ((float4*)g_xp)[(size_t)row*76 + c] = v;
}

// ------------------------- weight prep: stack + pad + bias sum -------------------------
__global__ void prep_w_kernel(const float* __restrict__ wf, const float* __restrict__ wb,
                              const float* __restrict__ bif, const float* __restrict__ bhf,
                              const float* __restrict__ bib, const float* __restrict__ bhb)
{
    int i = blockIdx.x*blockDim.x + threadIdx.x;
    if (i >= NP*KP) return;
    int n = i / KP, k = i % KP;
    float v = 0.f;
    if (k < 300){
        if (n < 1200)      v = wf[n*300 + k];
        else if (n < 2400) v = wb[(n-1200)*300 + k];
    }
    g_wp[i] = v;
    if (k == 0){
        float b = 0.f;
        if (n < 1200)      b = bif[n] + bhf[n];
        else if (n < 2400) b = bib[n-1200] + bhb[n-1200];
        g_bs[n] = b;
    }
}

// ------------------------- generic transpose into scratch -------------------------
__global__ void transpose_kernel(const float* __restrict__ in, int R, int C, int which)
{
    float* out = (which==0) ? g_whhT_f : (which==1) ? g_whhT_b
               : (which==2) ? g_gwihT  : g_gwhhT;
    __shared__ float tile[32][33];
    int c0 = blockIdx.x*32, r0 = blockIdx.y*32;
    int x = threadIdx.x, y = threadIdx.y;
    #pragma unroll
    for (int i = 0; i < 32; i += 8){
        int r = r0 + y + i, c = c0 + x;
        if (r < R && c < C) tile[y+i][x] = in[(size_t)r*C + c];
    }
    __syncthreads();
    #pragma unroll
    for (int i = 0; i < 32; i += 8){
        int r = r0 + x, c = c0 + y + i;
        if (r < R && c < C) out[(size_t)c*R + r] = tile[x][y+i];
    }
}

// ------------------------- merged input GEMM: pre = Xp(32768,304) @ Wp(2432,304)^T + bs -----
__global__ void __launch_bounds__(256,2) gemm_pre_kernel()
{
    __shared__ float As[2][8][132];
    __shared__ float Bs[2][8][132];
    int t  = threadIdx.x;             // 256
    int n0 = blockIdx.x * 128;
    int m0 = blockIdx.y * 128;
    int tx = t & 15, ty = t >> 4;
    int lr = t >> 1;                  // 0..127
    int lk = (t & 1) * 4;             // 0 or 4
    const float* Ap = g_xp + (size_t)(m0+lr)*KP + lk;
    const float* Bp = g_wp + (size_t)(n0+lr)*KP + lk;

    float4 va = *(const float4*)Ap;
    float4 vb = *(const float4*)Bp;
    As[0][lk  ][lr]=va.x; As[0][lk+1][lr]=va.y; As[0][lk+2][lr]=va.z; As[0][lk+3][lr]=va.w;
    Bs[0][lk  ][lr]=vb.x; Bs[0][lk+1][lr]=vb.y; Bs[0][lk+2][lr]=vb.z; Bs[0][lk+3][lr]=vb.w;
    __syncthreads();

    float acc[8][8];
    #pragma unroll
    for (int i = 0; i < 8; i++)
        #pragma unroll
        for (int j = 0; j < 8; j++) acc[i][j] = 0.f;

    const int NT = KP/8; // 38
    for (int kt = 0; kt < NT; kt++){
        int cur = kt & 1;
        if (kt+1 < NT){
            va = *(const float4*)(Ap + (kt+1)*8);
            vb = *(const float4*)(Bp + (kt+1)*8);
        }
        #pragma unroll
        for (int kk = 0; kk < 8; kk++){
            float a[8], bb[8];
            *(float4*)&a[0]  = *(const float4*)&As[cur][kk][ty*8];
            *(float4*)&a[4]  = *(const float4*)&As[cur][kk][ty*8+4];
            *(float4*)&bb[0] = *(const float4*)&Bs[cur][kk][tx*8];
            *(float4*)&bb[4] = *(const float4*)&Bs[cur][kk][tx*8+4];
            #pragma unroll
            for (int i = 0; i < 8; i++)
                #pragma unroll
                for (int j = 0; j < 8; j++)
                    acc[i][j] += a[i]*bb[j];
        }
        if (kt+1 < NT){
            int nxt = cur ^ 1;
            As[nxt][lk  ][lr]=va.x; As[nxt][lk+1][lr]=va.y; As[nxt][lk+2][lr]=va.z; As[nxt][lk+3][lr]=va.w;
            Bs[nxt][lk  ][lr]=vb.x; Bs[nxt][lk+1][lr]=vb.y; Bs[nxt][lk+2][lr]=vb.z; Bs[nxt][lk+3][lr]=vb.w;
        }
        __syncthreads();
    }

    float bsv[8];
    #pragma unroll
    for (int j = 0; j < 8; j++) bsv[j] = g_bs[n0 + tx*8 + j];
    #pragma unroll
    for (int i = 0; i < 8; i++){
        size_t gm = (size_t)(m0 + ty*8 + i);
        float* cp = g_pre + gm*NP + n0 + tx*8;
        float4 o0, o1;
        o0.x = acc[i][0]+bsv[0]; o0.y = acc[i][1]+bsv[1];
        o0.z = acc[i][2]+bsv[2]; o0.w = acc[i][3]+bsv[3];
        o1.x = acc[i][4]+bsv[4]; o1.y = acc[i][5]+bsv[5];
        o1.z = acc[i][6]+bsv[6]; o1.w = acc[i][7]+bsv[7];
        *(float4*)cp     = o0;
        *(float4*)(cp+4) = o1;
    }
}

// ------------------------- persistent BiLSTM recurrence (paired h-split) -------------------------
// 128 blocks: bid = (pair<<1)|half; pair: dir = pair>>5, bg = pair&31 (8 batch rows each).
// Each block owns 150 h-indices (its half) x 4 gates x 8 batch rows.
// Per step: gates from pre + Whh@h (full h in smem), update own half, exchange halves
// with partner via global double buffer + monotonic flag sync (all blocks co-resident).
__global__ void __launch_bounds__(640,1) lstm_kernel()
{
    extern __shared__ float sm[];
    float (*h_s)[8]      = (float(*)[8])sm;                       // [300][8]
    float (*c_s)[152]    = (float(*)[152])(sm + 2400);            // [8][152]
    float (*ga)[8][152]  = (float(*)[8][152])(sm + 2400 + 8*152); // [4][8][152]
    int*  len_s          = (int*)(sm + 2400 + 8*152 + 4*8*152);

    int bid  = blockIdx.x;
    int half = bid & 1;
    int pr   = bid >> 1;
    int dir  = pr >> 5;
    int bg   = pr & 31;
    int b0   = bg * 8;
    int partner = bid ^ 1;

    const float* pre  = g_pre + dir*1200;
    const float* whhT = dir ? g_whhT_b : g_whhT_f;
    float* out        = dir ? g_outrev : g_outf;
    const size_t PAR  = (size_t)2*32*300*8;
    float* hxbase     = g_hx + ((size_t)(dir*32 + bg))*2400;

    int t = threadIdx.x;
    if (t < 8) len_s[t] = g_len[b0 + t];
    for (int i = t; i < 2400; i += 640) ((float*)h_s)[i] = 0.f;
    for (int i = t; i < 8*152; i += 640) ((float*)c_s)[i] = 0.f;
    __syncthreads();

    int len[8];
    #pragma unroll
    for (int r = 0; r < 8; r++) len[r] = len_s[r];
    int maxlen = 0;
    #pragma unroll
    for (int r = 0; r < 8; r++) maxlen = max(maxlen, len[r]);

    int g  = t / 150;          // gate 0..3 (t<600)
    int jj = t % 150;
    int row = g*300 + half*150 + jj;
    bool active = (t < 600);

    for (int step = 0; step < maxlen; step++){
        // ---- gate phase ----
        if (active){
            float acc[8];
            #pragma unroll
            for (int r = 0; r < 8; r++){
                int L = len[r];
                if (step < L){
                    int pos = dir ? (L-1-step) : step;
                    acc[r] = pre[(size_t)((b0+r)*Sn + pos)*NP + row];
                } else acc[r] = 0.f;
            }
            if (step > 0){
                const float* wp = whhT + row;
                #pragma unroll 4
                for (int k = 0; k < Hn; k++){
                    float w = wp[(size_t)k*NG];
                    float4 ha = *(const float4*)&h_s[k][0];
                    float4 hb = *(const float4*)&h_s[k][4];
                    acc[0] += w*ha.x; acc[1] += w*ha.y;
                    acc[2] += w*ha.z; acc[3] += w*ha.w;
                    acc[4] += w*hb.x; acc[5] += w*hb.y;
                    acc[6] += w*hb.z; acc[7] += w*hb.w;
                }
            }
            if (g == 2){
                #pragma unroll
                for (int r = 0; r < 8; r++) ga[2][r][jj] = tanhf(acc[r]);
            } else {
                #pragma unroll
                for (int r = 0; r < 8; r++) ga[g][r][jj] = sigf(acc[r]);
            }
        }
        __syncthreads();

        // ---- update + publish own half ----
        float* hxp = hxbase + (size_t)(step & 1) * PAR;
        for (int idx = t; idx < 1200; idx += 640){
            int r = idx / 150, jq = idx % 150;
            int j = half*150 + jq;
            float* op = out + (size_t)((b0+r)*Sn + step)*Hn + j;
            float hval;
            if (step < len[r]){
                float c = ga[1][r][jq]*c_s[r][jq] + ga[0][r][jq]*ga[2][r][jq];
                hval = ga[3][r][jq]*tanhf(c);
                c_s[r][jq] = c;
                h_s[j][r] = hval;
                *op = hval;
            } else {
                hval = h_s[j][r];
                *op = 0.f;
            }
            __stcg(&hxp[j*8 + r], hval);
        }
        __threadfence();
        __syncthreads();
        if (t == 0){
            atomicExch(&g_sync[bid], (unsigned)(step+1));
            while (atomicAdd(&g_sync[partner], 0u) <= (unsigned)step) { }
        }
        __syncthreads();
        // ---- read partner half ----
        for (int idx = t; idx < 1200; idx += 640){
            int r = idx / 150, jq = idx % 150;
            int j = (1-half)*150 + jq;
            h_s[j][r] = __ldcg(&hxp[j*8 + r]);
        }
        __syncthreads();
    }

    // ---- tail: zero outputs for steps >= maxlen ----
    for (int step = maxlen; step < Sn; step++){
        for (int idx = t; idx < 1200; idx += 640){
            int r = idx / 150, jq = idx % 150;
            int j = half*150 + jq;
            out[(size_t)((b0+r)*Sn + step)*Hn + j] = 0.f;
        }
    }
}

// ------------------------- locationed memory -------------------------
__global__ void locmem_kernel()
{
    int b = blockIdx.x;
    int s = blockIdx.y;
    int mlen = g_len[b];
    int llen = g_len[Bn+b];
    int alen = g_len[2*Bn+b];
    int a_s = llen, a_e = llen + alen;
    float u, l;
    if (s < a_s)      { u = (float)(s - a_s); l = (float)(a_s - s); }
    else if (s < a_e) { u = 0.f; l = 0.f; }
    else              { u = (float)(s - a_e + 1); l = u; }
    bool valid = s < mlen;
    if (!valid) u = 0.f;
    float w = valid ? (1.f - l/(float)mlen) : 1.f;

    float* mo = g_mem + ((size_t)b*Sn + s)*Dn;
    const float* of = g_outf + ((size_t)b*Sn + s)*Hn;
    const float* orv = valid ? (g_outrev + ((size_t)b*Sn + (mlen-1-s))*Hn) : (const float*)0;
    int t = threadIdx.x;
    for (int d = t; d < Dn; d += blockDim.x){
        float v;
        if (d < Hn)        v = of[d] * w;
        else if (d < 2*Hn) v = (orv ? orv[d-Hn] : 0.f) * w;
        else               v = u;
        mo[d] = v;
    }
}

// ------------------------- aspect mean + et init -------------------------
__global__ void aspect_kernel(const int* __restrict__ aidx, const float* __restrict__ emb)
{
    int b = blockIdx.x;
    int t = threadIdx.x; // 320
    if (t < En){
        float s = 0.f;
        #pragma unroll
        for (int jj = 0; jj < ASn; jj++){
            int v = aidx[b*ASn + jj];
            s += emb[(size_t)v*En + t];
        }
        g_aspect[b*En + t] = s / (float)g_len[2*Bn + b];
        g_et[b*En + t] = 0.f;
    }
}

// ------------------------- attention (per hop): g, softmax, i_t -------------------------
__global__ void att_kernel(const float* __restrict__ att_w, const float* __restrict__ att_b)
{
    int b = blockIdx.x;
    int t = threadIdx.x; // 256
    __shared__ float red[256];
    __shared__ float alpha[Sn];
    __shared__ float base_s;

    float p = 0.f;
    for (int d = t; d < En; d += 256)
        p += g_et[b*En+d]*att_w[Dn+d] + g_aspect[b*En+d]*att_w[Dn+En+d];
    red[t] = p; __syncthreads();
    for (int s = 128; s > 0; s >>= 1){ if (t < s) red[t] += red[t+s]; __syncthreads(); }
    if (t == 0) base_s = red[0] + att_b[0];
    __syncthreads();

    int warp = t >> 5, lane = t & 31;
    for (int s = warp; s < Sn; s += 8){
        const float* mrow = g_mem + ((size_t)b*Sn + s)*Dn;
        float acc = 0.f;
        for (int d = lane; d < Dn; d += 32) acc += mrow[d]*att_w[d];
        #pragma unroll
        for (int o = 16; o > 0; o >>= 1) acc += __shfl_down_sync(0xffffffffu, acc, o);
        if (lane == 0) alpha[s] = acc + base_s;
    }
    __syncthreads();

    red[t] = (t < Sn) ? alpha[t] : -1e30f;
    __syncthreads();
    for (int s = 128; s > 0; s >>= 1){ if (t < s) red[t] = fmaxf(red[t], red[t+s]); __syncthreads(); }
    float mx = red[0]; __syncthreads();
    float e = 0.f;
    if (t < Sn){ e = expf(alpha[t] - mx); alpha[t] = e; }
    red[t] = e; __syncthreads();
    for (int s = 128; s > 0; s >>= 1){ if (t < s) red[t] += red[t+s]; __syncthreads(); }
    float inv = 1.f / red[0]; __syncthreads();
    if (t < Sn) alpha[t] *= inv;
    __syncthreads();

    for (int d = t; d < Dn; d += 256){
        float acc = 0.f;
        const float* mp = g_mem + (size_t)b*Sn*Dn + d;
        #pragma unroll 4
        for (int s = 0; s < Sn; s++) acc += alpha[s]*mp[(size_t)s*Dn];
        g_it[b*Dn + d] = acc;
    }
}

// ------------------------- GRU cell (per hop): 4 batches per block -------------------------
__global__ void gru_kernel(const float* __restrict__ b_ih, const float* __restrict__ b_hh)
{
    int b0 = blockIdx.x * 4;   // 64 blocks
    int t = threadIdx.x;       // 320
    __shared__ float it_s[4][604];
    __shared__ float et_s[4][304];
    for (int i = t; i < 4*Dn; i += 320){ int r = i/Dn, d = i%Dn; it_s[r][d] = g_it[(b0+r)*Dn + d]; }
    for (int i = t; i < 4*En; i += 320){ int r = i/En, d = i%En; et_s[r][d] = g_et[(b0+r)*En + d]; }
    __syncthreads();
    if (t < 300){
        int j = t;
        float gi0[4], gi1[4], gi2[4], gh0[4], gh1[4], gh2[4];
        float bi0 = b_ih[j], bi1 = b_ih[300+j], bi2 = b_ih[600+j];
        float bh0 = b_hh[j], bh1 = b_hh[300+j], bh2 = b_hh[600+j];
        #pragma unroll
        for (int r = 0; r < 4; r++){
            gi0[r]=bi0; gi1[r]=bi1; gi2[r]=bi2;
            gh0[r]=bh0; gh1[r]=bh1; gh2[r]=bh2;
        }
        const float* wp = g_gwihT + j;
        #pragma unroll 2
        for (int d = 0; d < Dn; d++){
            float w0 = wp[(size_t)d*900];
            float w1 = wp[(size_t)d*900 + 300];
            float w2 = wp[(size_t)d*900 + 600];
            #pragma unroll
            for (int r = 0; r < 4; r++){
                float x = it_s[r][d];
                gi0[r] += w0*x; gi1[r] += w1*x; gi2[r] += w2*x;
            }
        }
        const float* hp = g_gwhhT + j;
        #pragma unroll 2
        for (int d = 0; d < En; d++){
            float w0 = hp[(size_t)d*900];
            float w1 = hp[(size_t)d*900 + 300];
            float w2 = hp[(size_t)d*900 + 600];
            #pragma unroll
            for (int r = 0; r < 4; r++){
                float x = et_s[r][d];
                gh0[r] += w0*x; gh1[r] += w1*x; gh2[r] += w2*x;
            }
        }
        #pragma unroll
        for (int r = 0; r < 4; r++){
            float rr = sigf(gi0[r] + gh0[r]);
            float z  = sigf(gi1[r] + gh1[r]);
            float n  = tanhf(gi2[r] + rr*gh2[r]);
            g_et[(b0+r)*En + j] = (1.f - z)*n + z*et_s[r][j];
        }
    }
}

// ------------------------- dense head -------------------------
__global__ void dense_kernel(const float* __restrict__ dw, const float* __restrict__ db,
                             float* __restrict__ out)
{
    int b = blockIdx.x;
    int t = threadIdx.x; // 96
    int p = t >> 5, lane = t & 31;
    float acc = 0.f;
    for (int d = lane; d < En; d += 32) acc += g_et[b*En + d]*dw[p*En + d];
    #pragma unroll
    for (int o = 16; o > 0; o >>= 1) acc += __shfl_down_sync(0xffffffffu, acc, o);
    if (lane == 0) out[b*Pn + p] = acc + db[p];
}

// ------------------------- launch -------------------------
extern "C" void kernel_launch(void* const* d_in, const int* in_sizes, int n_in,
                              void* d_out, int out_size)
{
    const int*   raw    = (const int*)d_in[0];
    const int*   aidx   = (const int*)d_in[1];
    const int*   left   = (const int*)d_in[2];
    const float* emb    = (const float*)d_in[3];
    const float* w_ih_f = (const float*)d_in[4];
    const float* w_hh_f = (const float*)d_in[5];
    const float* b_ih_f = (const float*)d_in[6];
    const float* b_hh_f = (const float*)d_in[7];
    const float* w_ih_b = (const float*)d_in[8];
    const float* w_hh_b = (const float*)d_in[9];
    const float* b_ih_b = (const float*)d_in[10];
    const float* b_hh_b = (const float*)d_in[11];
    const float* att_w  = (const float*)d_in[12];
    const float* att_b  = (const float*)d_in[13];
    const float* gw_ih  = (const float*)d_in[14];
    const float* gw_hh  = (const float*)d_in[15];
    const float* gb_ih  = (const float*)d_in[16];
    const float* gb_hh  = (const float*)d_in[17];
    const float* dw     = (const float*)d_in[18];
    const float* db     = (const float*)d_in[19];
    float* out = (float*)d_out;

    static bool attr_set = false;
    if (!attr_set){
        cudaFuncSetAttribute(lstm_kernel, cudaFuncAttributeMaxDynamicSharedMemorySize, 72*1024);
        attr_set = true;
    }

    lengths_kernel<<<Bn, Sn>>>(raw, aidx, left);
    zero_sync_kernel<<<1, 128>>>();
    embed_kernel<<<(Bn*Sn*76 + 255)/256, 256>>>(raw, emb);
    prep_w_kernel<<<(NP*KP + 255)/256, 256>>>(w_ih_f, w_ih_b, b_ih_f, b_hh_f, b_ih_b, b_hh_b);

    transpose_kernel<<<dim3(10,38), dim3(32,8)>>>(w_hh_f, NG, Hn, 0);
    transpose_kernel<<<dim3(10,38), dim3(32,8)>>>(w_hh_b, NG, Hn, 1);
    transpose_kernel<<<dim3(19,29), dim3(32,8)>>>(gw_ih, 900, Dn, 2);
    transpose_kernel<<<dim3(10,29), dim3(32,8)>>>(gw_hh, 900, Hn, 3);

    gemm_pre_kernel<<<dim3(NP/128, 256), 256>>>();

    const int lstm_smem = (2400 + 8*152 + 4*8*152)*4 + 64;
    lstm_kernel<<<128, 640, lstm_smem>>>();

    locmem_kernel<<<dim3(Bn,Sn), 256>>>();
    aspect_kernel<<<Bn, 320>>>(aidx, emb);

    for (int hop = 0; hop < 3; hop++){
        att_kernel<<<Bn, 256>>>(att_w, att_b);
        gru_kernel<<<64, 320>>>(gb_ih, gb_hh);
    }
    dense_kernel<<<Bn, 96>>>(dw, db, out);
}